// round 7
// baseline (speedup 1.0000x reference)
#include <cuda_runtime.h>
#include <cuda_bf16.h>
#include <cstdint>

// ============================================================================
// CrossAttentionBlock — 4-kernel split (sm_100a), permuted-tf32 fragment layout
//   K0: weights -> tf32(rna) bits, k-chunk permuted (fragment = 1x LDS/LDG.128)
//   K1: projections, cp.async 3-stage pipeline, K-chunk=32 (half the syncs)
//   K2: y_i = sum_j 2^(ph_i*th_j) g_j / sum_j 2^(ph_i*th_j); writes y permuted
//   K3: out = y@W_w^T + W_b + x0; W in smem, y fragments via LDG.128 from L2
// ============================================================================

namespace {
constexpr int kB   = 16384;
constexpr int kC   = 1024;
constexpr int kD   = 128;
constexpr float kLog2e = 1.4426950408889634f;

// K1 smem: per stage, A = 2 sub-chunks of [128][20], W = 2 sub-chunks of [128][16]
constexpr int kASubW   = 128 * 20;                 // 2560 words
constexpr int kAStageW = 2 * kASubW;               // 5120
constexpr int kWSubW   = 128 * 16;                 // 2048
constexpr int kWStageW = 2 * kWSubW;               // 4096
constexpr int kWBaseW  = 3 * kAStageW;             // 15360
constexpr int kK1Smem  = (3 * kAStageW + 3 * kWStageW) * 4;  // 110592 B

// K3 smem: W tile only, 8 sub-blocks of [128][16] words = 64 KB
constexpr int kK3Smem  = 8 * 2048 * 4;             // 65536 B
}  // namespace

// inter-kernel scratch
__device__ float    g_glob[kB * kD];
__device__ float    th_glob[kB * kD];        // pre-scaled by log2e
__device__ float    ph_glob[kB * kD];
__device__ float    y_glob[kB * kD];         // tf32 bits, k-chunk permuted
__device__ uint32_t w_glob[3 * kD * kC];     // proj weights tf32, permuted
__device__ uint32_t w3_glob[kC * kD];        // W_w tf32, permuted

__device__ __forceinline__ uint32_t f2tf(float f) {
    uint32_t u;
    asm("cvt.rna.tf32.f32 %0, %1;" : "=r"(u) : "f"(f));
    return u;
}
__device__ __forceinline__ float fast_ex2(float x) {
    float r;
    asm("ex2.approx.ftz.f32 %0, %1;" : "=f"(r) : "f"(x));
    return r;
}
__device__ __forceinline__ float fast_rcp(float x) {
    float r;
    asm("rcp.approx.ftz.f32 %0, %1;" : "=f"(r) : "f"(x));
    return r;
}
__device__ __forceinline__ void mma_tf32(float c[4],
                                         uint32_t a0, uint32_t a1,
                                         uint32_t a2, uint32_t a3,
                                         uint32_t b0, uint32_t b1) {
    asm volatile(
        "mma.sync.aligned.m16n8k8.row.col.f32.tf32.tf32.f32 "
        "{%0,%1,%2,%3},{%4,%5,%6,%7},{%8,%9},{%0,%1,%2,%3};"
        : "+f"(c[0]), "+f"(c[1]), "+f"(c[2]), "+f"(c[3])
        : "r"(a0), "r"(a1), "r"(a2), "r"(a3), "r"(b0), "r"(b1));
}
__device__ __forceinline__ void cp16(uint32_t dst, const void* src) {
    asm volatile("cp.async.cg.shared.global [%0], [%1], 16;" :: "r"(dst), "l"(src));
}
__device__ __forceinline__ void cp_commit() {
    asm volatile("cp.async.commit_group;");
}
template <int N>
__device__ __forceinline__ void cp_wait() {
    asm volatile("cp.async.wait_group %0;" :: "n"(N));
}
__device__ __forceinline__ uint32_t smem_u32(const void* p) {
    uint32_t a;
    asm("{ .reg .u64 t; cvta.to.shared.u64 t, %1; cvt.u32.u64 %0, t; }"
        : "=r"(a) : "l"(p));
    return a;
}
// permuted position of column col (within its 16-word chunk)
__device__ __forceinline__ int permc(int col) {
    return (col & ~15) | ((col & 3) << 2) | ((col >> 2) & 3);
}

// ========== K0: weight pre-convert to permuted tf32 (rna) ==========
__global__ void __launch_bounds__(256)
conv_w_kernel(const float* __restrict__ g_w, const float* __restrict__ th_w,
              const float* __restrict__ ph_w, const float* __restrict__ Ww) {
    int i4 = blockIdx.x * 256 + threadIdx.x;
    if (i4 < 98304) {
        int head = i4 >> 15;
        int loc  = i4 & 32767;
        const float4* src = (head == 0) ? reinterpret_cast<const float4*>(g_w)
                          : (head == 1) ? reinterpret_cast<const float4*>(th_w)
                                        : reinterpret_cast<const float4*>(ph_w);
        float4 v = src[loc];
        float s = (head == 1) ? kLog2e : 1.0f;
        int wb  = loc * 4;
        int col = wb & (kC - 1);
        int q   = (col & 15) >> 2;
        uint32_t* dst = w_glob + head * kD * kC + (wb & ~15) + q;
        dst[0]  = f2tf(v.x * s);
        dst[4]  = f2tf(v.y * s);
        dst[8]  = f2tf(v.z * s);
        dst[12] = f2tf(v.w * s);
    } else {
        int loc = i4 - 98304;
        float4 v = reinterpret_cast<const float4*>(Ww)[loc];
        int wb  = loc * 4;
        int col = wb & (kD - 1);
        int q   = (col & 15) >> 2;
        uint32_t* dst = w3_glob + (wb & ~15) + q;
        dst[0]  = f2tf(v.x);
        dst[4]  = f2tf(v.y);
        dst[8]  = f2tf(v.z);
        dst[12] = f2tf(v.w);
    }
}

// ========== K1: projections, cp.async 3-stage, K-chunk=32, tile 128x128 ==========
__global__ void __launch_bounds__(256, 2)
proj_kernel(const float* __restrict__ x0, const float* __restrict__ x1,
            const float* __restrict__ g_b, const float* __restrict__ th_b,
            const float* __restrict__ ph_b) {
    extern __shared__ uint32_t sm[];

    const int tid  = threadIdx.x;
    const int lane = tid & 31;
    const int wid  = tid >> 5;
    const int gid  = lane >> 2;
    const int tig  = lane & 3;
    const int wm   = wid >> 1;
    const int wn   = wid & 1;
    const int row0 = blockIdx.x * 128;
    const int by   = blockIdx.y;

    const float* A = (by == 0) ? x0 : x1;
    const uint32_t* W = w_glob + (size_t)by * kD * kC;

    const int r0 = tid >> 2;           // 0..63
    const int c4 = (tid & 3) * 4;      // 0,4,8,12
    const float*    srcA = A + (size_t)(row0 + r0) * kC + c4;
    const uint32_t* srcW = W + (size_t)r0 * kC + c4;
    const uint32_t base = smem_u32(sm);
    const uint32_t dA0 = base + (r0 * 20 + c4) * 4;
    const uint32_t dW0 = base + (kWBaseW + r0 * 16 + c4) * 4;
    const uint32_t kAHalf = 64 * 20 * 4;
    const uint32_t kWHalf = 64 * 16 * 4;

    auto issue = [&](int stage, int kc32) {
        uint32_t sa = stage * (kAStageW * 4);
        uint32_t sw = stage * (kWStageW * 4);
#pragma unroll
        for (int sub = 0; sub < 2; sub++) {
            int kc = kc32 * 2 + sub;
            const float*    pa = srcA + kc * 16;
            const uint32_t* pw = srcW + kc * 16;
            uint32_t oa = sa + sub * (kASubW * 4);
            uint32_t ow = sw + sub * (kWSubW * 4);
            cp16(dA0 + oa, pa);
            cp16(dA0 + oa + kAHalf, pa + 64 * kC);
            cp16(dW0 + ow, pw);
            cp16(dW0 + ow + kWHalf, pw + 64 * kC);
        }
        cp_commit();
    };

    issue(0, 0);
    issue(1, 1);

    float acc[2][8][4];
#pragma unroll
    for (int a = 0; a < 2; a++)
#pragma unroll
        for (int b = 0; b < 8; b++)
#pragma unroll
            for (int ci = 0; ci < 4; ci++) acc[a][b][ci] = 0.f;

    int buf = 0;
#pragma unroll 1
    for (int kc = 0; kc < 32; kc++) {
        if (kc < 30) cp_wait<1>(); else cp_wait<0>();
        __syncthreads();
        if (kc + 2 < 32) {
            int ns = buf + 2; if (ns >= 3) ns -= 3;
            issue(ns, kc + 2);
        }
#pragma unroll
        for (int sub = 0; sub < 2; sub++) {
            const uint32_t* aS = sm + buf * kAStageW + sub * kASubW;
            const uint32_t* wS = sm + kWBaseW + buf * kWStageW + sub * kWSubW;

            uint32_t a0[2][4], a1[2][4];
#pragma unroll
            for (int mt = 0; mt < 2; mt++) {
                const uint32_t* p = aS + (wm * 32 + mt * 16 + gid) * 20 + tig;
                a0[mt][0] = p[0];    a0[mt][1] = p[8 * 20];
                a0[mt][2] = p[4];    a0[mt][3] = p[8 * 20 + 4];
                a1[mt][0] = p[8];    a1[mt][1] = p[8 * 20 + 8];
                a1[mt][2] = p[12];   a1[mt][3] = p[8 * 20 + 12];
            }
#pragma unroll
            for (int grp = 0; grp < 2; grp++) {
                uint4 bf[4];
#pragma unroll
                for (int j = 0; j < 4; j++) {
                    int nt = grp * 4 + j;
                    bf[j] = *reinterpret_cast<const uint4*>(
                        wS + (wn * 64 + nt * 8 + gid) * 16 + tig * 4);
                }
#pragma unroll
                for (int j = 0; j < 4; j++) {
                    int nt = grp * 4 + j;
                    mma_tf32(acc[0][nt], a0[0][0], a0[0][1], a0[0][2], a0[0][3], bf[j].x, bf[j].y);
                    mma_tf32(acc[1][nt], a0[1][0], a0[1][1], a0[1][2], a0[1][3], bf[j].x, bf[j].y);
                    mma_tf32(acc[0][nt], a1[0][0], a1[0][1], a1[0][2], a1[0][3], bf[j].z, bf[j].w);
                    mma_tf32(acc[1][nt], a1[1][0], a1[1][1], a1[1][2], a1[1][3], bf[j].z, bf[j].w);
                }
            }
        }
        buf++; if (buf == 3) buf = 0;
    }

    const float* bias = (by == 0) ? g_b : (by == 1) ? th_b : ph_b;
    const float bscale = (by == 1) ? kLog2e : 1.0f;
    float* outp = (by == 0) ? g_glob : (by == 1) ? th_glob : ph_glob;
#pragma unroll
    for (int mt = 0; mt < 2; mt++)
#pragma unroll
        for (int nt = 0; nt < 8; nt++)
#pragma unroll
            for (int ci = 0; ci < 4; ci++) {
                int r = wm * 32 + mt * 16 + gid + ((ci >= 2) ? 8 : 0);
                int n = wn * 64 + nt * 8 + tig * 2 + (ci & 1);
                outp[(size_t)(row0 + r) * kD + n] =
                    acc[mt][nt][ci] + bias[n] * bscale;
            }
}

// ========================= K2: attention (MUFU-bound) =========================
__global__ void __launch_bounds__(256)
attn_kernel() {
    __shared__ float tgs[8][256];

    const int lane = threadIdx.x & 31;
    const int wid  = threadIdx.x >> 5;
    const int r    = blockIdx.x * 8 + wid;

    {
        float4 t4 = *reinterpret_cast<const float4*>(th_glob + (size_t)r * kD + lane * 4);
        float4 g4 = *reinterpret_cast<const float4*>(g_glob + (size_t)r * kD + lane * 4);
        float4* d = reinterpret_cast<float4*>(&tgs[wid][lane * 8]);
        d[0] = make_float4(t4.x, g4.x, t4.y, g4.y);
        d[1] = make_float4(t4.z, g4.z, t4.w, g4.w);
    }
    const float* pr = ph_glob + (size_t)r * kD;
    float p0 = pr[lane], p1 = pr[lane + 32], p2 = pr[lane + 64], p3 = pr[lane + 96];
    __syncwarp();

    const float2* tgr = reinterpret_cast<const float2*>(tgs[wid]);
    float n0 = 0.f, n1 = 0.f, n2 = 0.f, n3 = 0.f;
    float d0 = 0.f, d1 = 0.f, d2 = 0.f, d3 = 0.f;
#pragma unroll 8
    for (int j = 0; j < kD; j++) {
        float2 t = tgr[j];
        float e0 = fast_ex2(p0 * t.x);
        float e1 = fast_ex2(p1 * t.x);
        float e2 = fast_ex2(p2 * t.x);
        float e3 = fast_ex2(p3 * t.x);
        d0 += e0; d1 += e1; d2 += e2; d3 += e3;
        n0 = fmaf(e0, t.y, n0);
        n1 = fmaf(e1, t.y, n1);
        n2 = fmaf(e2, t.y, n2);
        n3 = fmaf(e3, t.y, n3);
    }
    float* yr = y_glob + (size_t)r * kD;
    yr[permc(lane)]      = __uint_as_float(f2tf(n0 * fast_rcp(d0)));
    yr[permc(lane + 32)] = __uint_as_float(f2tf(n1 * fast_rcp(d1)));
    yr[permc(lane + 64)] = __uint_as_float(f2tf(n2 * fast_rcp(d2)));
    yr[permc(lane + 96)] = __uint_as_float(f2tf(n3 * fast_rcp(d3)));
}

// ====== K3: out = y@W_w^T + W_b + x0 — W in smem, y via LDG.128 from L2 ======
// grid (128 row-tiles, 8 col-tiles), 256 thr, tile 128x128.
__global__ void __launch_bounds__(256, 2)
out_kernel(const float* __restrict__ x0, const float* __restrict__ Wb,
           float* __restrict__ out) {
    extern __shared__ uint32_t wbuf[];   // 8 sub-blocks of [128][16]

    const int tid  = threadIdx.x;
    const int lane = tid & 31;
    const int wid  = tid >> 5;
    const int gid  = lane >> 2;
    const int tig  = lane & 3;
    const int wm   = wid >> 1;           // 0..3 (32 rows)
    const int wn   = wid & 1;            // 0..1 (64 cols)
    const int row0 = blockIdx.x * 128;
    const int col0 = blockIdx.y * 128;

    // stage W tile [col0..col0+128) x 128 k-words: 4096 float4 / 256 thr
    {
        const uint32_t base = smem_u32(wbuf);
        const int r8 = tid >> 5;                 // 0..7
        const int cc = (tid & 31) * 4;           // word col 0..124
        const int sub = cc >> 4;                 // 0..7
        const int ccin = cc & 15;
#pragma unroll
        for (int i = 0; i < 16; i++) {
            int n = i * 8 + r8;                  // 0..127
            cp16(base + (sub * 2048 + n * 16 + ccin) * 4,
                 w3_glob + (size_t)(col0 + n) * kD + cc);
        }
        cp_commit();
    }
    cp_wait<0>();
    __syncthreads();

    float acc[2][8][4];
#pragma unroll
    for (int a = 0; a < 2; a++)
#pragma unroll
        for (int b = 0; b < 8; b++)
#pragma unroll
            for (int c = 0; c < 4; c++) acc[a][b][c] = 0.f;

    const int rbase = wm * 32;
    const uint32_t* y0 = reinterpret_cast<const uint32_t*>(y_glob) +
                         (size_t)(row0 + rbase + gid) * kD + tig * 4;
    // prefetch chunk 0 fragments (L2-resident y, contiguous via permuted layout)
    uint4 av[2][2];
#pragma unroll
    for (int mt = 0; mt < 2; mt++) {
        av[mt][0] = *reinterpret_cast<const uint4*>(y0 + (mt * 16) * kD);
        av[mt][1] = *reinterpret_cast<const uint4*>(y0 + (mt * 16 + 8) * kD);
    }

#pragma unroll 1
    for (int c = 0; c < 8; c++) {
        uint4 nx[2][2];
        if (c < 7) {
#pragma unroll
            for (int mt = 0; mt < 2; mt++) {
                nx[mt][0] = *reinterpret_cast<const uint4*>(y0 + (mt * 16) * kD + (c + 1) * 16);
                nx[mt][1] = *reinterpret_cast<const uint4*>(y0 + (mt * 16 + 8) * kD + (c + 1) * 16);
            }
        }
        const uint32_t* wS = wbuf + c * 2048;
#pragma unroll
        for (int grp = 0; grp < 2; grp++) {
            uint4 bv[4];
#pragma unroll
            for (int j = 0; j < 4; j++) {
                int nt = grp * 4 + j;
                bv[j] = *reinterpret_cast<const uint4*>(
                    wS + (wn * 64 + nt * 8 + gid) * 16 + tig * 4);
            }
#pragma unroll
            for (int j = 0; j < 4; j++) {
                int nt = grp * 4 + j;
#pragma unroll
                for (int mt = 0; mt < 2; mt++) {
                    mma_tf32(acc[mt][nt], av[mt][0].x, av[mt][1].x,
                             av[mt][0].y, av[mt][1].y, bv[j].x, bv[j].y);
                    mma_tf32(acc[mt][nt], av[mt][0].z, av[mt][1].z,
                             av[mt][0].w, av[mt][1].w, bv[j].z, bv[j].w);
                }
            }
        }
        if (c < 7) {
#pragma unroll
            for (int mt = 0; mt < 2; mt++) {
                av[mt][0] = nx[mt][0];
                av[mt][1] = nx[mt][1];
            }
        }
    }

#pragma unroll
    for (int mt = 0; mt < 2; mt++)
#pragma unroll
        for (int nt = 0; nt < 8; nt++)
#pragma unroll
            for (int pair = 0; pair < 2; pair++) {
                int r = rbase + mt * 16 + gid + pair * 8;
                int n = col0 + wn * 64 + nt * 8 + tig * 2;
                float2 xx = *reinterpret_cast<const float2*>(
                    x0 + (size_t)(row0 + r) * kC + n);
                float2 o;
                o.x = acc[mt][nt][pair * 2 + 0] + Wb[n] + xx.x;
                o.y = acc[mt][nt][pair * 2 + 1] + Wb[n + 1] + xx.y;
                *reinterpret_cast<float2*>(out + (size_t)(row0 + r) * kC + n) = o;
            }
}

extern "C" void kernel_launch(void* const* d_in, const int* in_sizes, int n_in,
                              void* d_out, int out_size) {
    (void)in_sizes; (void)n_in; (void)out_size;
    const float* x0   = (const float*)d_in[0];
    const float* x1   = (const float*)d_in[1];
    const float* g_w  = (const float*)d_in[2];
    const float* g_b  = (const float*)d_in[3];
    const float* th_w = (const float*)d_in[4];
    const float* th_b = (const float*)d_in[5];
    const float* ph_w = (const float*)d_in[6];
    const float* ph_b = (const float*)d_in[7];
    const float* Ww   = (const float*)d_in[8];
    const float* Wb   = (const float*)d_in[9];
    float* out = (float*)d_out;

    cudaFuncSetAttribute(proj_kernel,
                         cudaFuncAttributeMaxDynamicSharedMemorySize, kK1Smem);
    cudaFuncSetAttribute(out_kernel,
                         cudaFuncAttributeMaxDynamicSharedMemorySize, kK3Smem);

    conv_w_kernel<<<512, 256>>>(g_w, th_w, ph_w, Ww);
    proj_kernel<<<dim3(128, 3), 256, kK1Smem>>>(x0, x1, g_b, th_b, ph_b);
    attn_kernel<<<2048, 256>>>();
    out_kernel<<<dim3(128, 8), 256, kK3Smem>>>(x0, Wb, out);
}

// round 8
// speedup vs baseline: 1.0011x; 1.0011x over previous
#include <cuda_runtime.h>
#include <cuda_bf16.h>
#include <cstdint>

// ============================================================================
// CrossAttentionBlock — 4-kernel split (sm_100a), permuted-tf32 fragment layout
//   K0: weights -> tf32(rna) bits, k-chunk permuted (fragment = 1x LDS/LDG.128)
//   K1: projections, cp.async 3-stage pipeline, K-chunk=32 (half the syncs)
//   K2: y_i = sum_j 2^(ph_i*th_j) g_j / sum_j 2^(ph_i*th_j); writes y permuted
//   K3: out = y@W_w^T + W_b + x0; W in smem, y fragments via LDG.128 from L2
// ============================================================================

namespace {
constexpr int kB   = 16384;
constexpr int kC   = 1024;
constexpr int kD   = 128;
constexpr float kLog2e = 1.4426950408889634f;

// K1 smem: per stage, A = 2 sub-chunks of [128][20], W = 2 sub-chunks of [128][16]
constexpr int kASubW   = 128 * 20;                 // 2560 words
constexpr int kAStageW = 2 * kASubW;               // 5120
constexpr int kWSubW   = 128 * 16;                 // 2048
constexpr int kWStageW = 2 * kWSubW;               // 4096
constexpr int kWBaseW  = 3 * kAStageW;             // 15360
constexpr int kK1Smem  = (3 * kAStageW + 3 * kWStageW) * 4;  // 110592 B

// K3 smem: W tile only, 8 sub-blocks of [128][16] words = 64 KB
constexpr int kK3Smem  = 8 * 2048 * 4;             // 65536 B
}  // namespace

// inter-kernel scratch
__device__ float    g_glob[kB * kD];
__device__ float    th_glob[kB * kD];        // pre-scaled by log2e
__device__ float    ph_glob[kB * kD];
__device__ float    y_glob[kB * kD];         // tf32 bits, k-chunk permuted
__device__ uint32_t w_glob[3 * kD * kC];     // proj weights tf32, permuted
__device__ uint32_t w3_glob[kC * kD];        // W_w tf32, permuted

__device__ __forceinline__ uint32_t f2tf(float f) {
    uint32_t u;
    asm("cvt.rna.tf32.f32 %0, %1;" : "=r"(u) : "f"(f));
    return u;
}
__device__ __forceinline__ float fast_ex2(float x) {
    float r;
    asm("ex2.approx.ftz.f32 %0, %1;" : "=f"(r) : "f"(x));
    return r;
}
__device__ __forceinline__ float fast_rcp(float x) {
    float r;
    asm("rcp.approx.ftz.f32 %0, %1;" : "=f"(r) : "f"(x));
    return r;
}
__device__ __forceinline__ void mma_tf32(float c[4],
                                         uint32_t a0, uint32_t a1,
                                         uint32_t a2, uint32_t a3,
                                         uint32_t b0, uint32_t b1) {
    asm volatile(
        "mma.sync.aligned.m16n8k8.row.col.f32.tf32.tf32.f32 "
        "{%0,%1,%2,%3},{%4,%5,%6,%7},{%8,%9},{%0,%1,%2,%3};"
        : "+f"(c[0]), "+f"(c[1]), "+f"(c[2]), "+f"(c[3])
        : "r"(a0), "r"(a1), "r"(a2), "r"(a3), "r"(b0), "r"(b1));
}
__device__ __forceinline__ void cp16(uint32_t dst, const void* src) {
    asm volatile("cp.async.cg.shared.global [%0], [%1], 16;" :: "r"(dst), "l"(src));
}
__device__ __forceinline__ void cp_commit() {
    asm volatile("cp.async.commit_group;");
}
template <int N>
__device__ __forceinline__ void cp_wait() {
    asm volatile("cp.async.wait_group %0;" :: "n"(N));
}
__device__ __forceinline__ uint32_t smem_u32(const void* p) {
    uint32_t a;
    asm("{ .reg .u64 t; cvta.to.shared.u64 t, %1; cvt.u32.u64 %0, t; }"
        : "=r"(a) : "l"(p));
    return a;
}
// permuted position of column col (within its 16-word chunk)
__device__ __forceinline__ int permc(int col) {
    return (col & ~15) | ((col & 3) << 2) | ((col >> 2) & 3);
}

// ========== K0: weight pre-convert to permuted tf32 (rna) ==========
__global__ void __launch_bounds__(256)
conv_w_kernel(const float* __restrict__ g_w, const float* __restrict__ th_w,
              const float* __restrict__ ph_w, const float* __restrict__ Ww) {
    int i4 = blockIdx.x * 256 + threadIdx.x;
    if (i4 < 98304) {
        int head = i4 >> 15;
        int loc  = i4 & 32767;
        const float4* src = (head == 0) ? reinterpret_cast<const float4*>(g_w)
                          : (head == 1) ? reinterpret_cast<const float4*>(th_w)
                                        : reinterpret_cast<const float4*>(ph_w);
        float4 v = src[loc];
        float s = (head == 1) ? kLog2e : 1.0f;
        int wb  = loc * 4;
        int col = wb & (kC - 1);
        int q   = (col & 15) >> 2;
        uint32_t* dst = w_glob + head * kD * kC + (wb & ~15) + q;
        dst[0]  = f2tf(v.x * s);
        dst[4]  = f2tf(v.y * s);
        dst[8]  = f2tf(v.z * s);
        dst[12] = f2tf(v.w * s);
    } else {
        int loc = i4 - 98304;
        float4 v = reinterpret_cast<const float4*>(Ww)[loc];
        int wb  = loc * 4;
        int col = wb & (kD - 1);
        int q   = (col & 15) >> 2;
        uint32_t* dst = w3_glob + (wb & ~15) + q;
        dst[0]  = f2tf(v.x);
        dst[4]  = f2tf(v.y);
        dst[8]  = f2tf(v.z);
        dst[12] = f2tf(v.w);
    }
}

// ========== K1: projections, cp.async 3-stage, K-chunk=32, tile 128x128 ==========
__global__ void __launch_bounds__(256, 2)
proj_kernel(const float* __restrict__ x0, const float* __restrict__ x1,
            const float* __restrict__ g_b, const float* __restrict__ th_b,
            const float* __restrict__ ph_b) {
    extern __shared__ uint32_t sm[];

    const int tid  = threadIdx.x;
    const int lane = tid & 31;
    const int wid  = tid >> 5;
    const int gid  = lane >> 2;
    const int tig  = lane & 3;
    const int wm   = wid >> 1;
    const int wn   = wid & 1;
    const int row0 = blockIdx.x * 128;
    const int by   = blockIdx.y;

    const float* A = (by == 0) ? x0 : x1;
    const uint32_t* W = w_glob + (size_t)by * kD * kC;

    const int r0 = tid >> 2;           // 0..63
    const int c4 = (tid & 3) * 4;      // 0,4,8,12
    const float*    srcA = A + (size_t)(row0 + r0) * kC + c4;
    const uint32_t* srcW = W + (size_t)r0 * kC + c4;
    const uint32_t base = smem_u32(sm);
    const uint32_t dA0 = base + (r0 * 20 + c4) * 4;
    const uint32_t dW0 = base + (kWBaseW + r0 * 16 + c4) * 4;
    const uint32_t kAHalf = 64 * 20 * 4;
    const uint32_t kWHalf = 64 * 16 * 4;

    auto issue = [&](int stage, int kc32) {
        uint32_t sa = stage * (kAStageW * 4);
        uint32_t sw = stage * (kWStageW * 4);
#pragma unroll
        for (int sub = 0; sub < 2; sub++) {
            int kc = kc32 * 2 + sub;
            const float*    pa = srcA + kc * 16;
            const uint32_t* pw = srcW + kc * 16;
            uint32_t oa = sa + sub * (kASubW * 4);
            uint32_t ow = sw + sub * (kWSubW * 4);
            cp16(dA0 + oa, pa);
            cp16(dA0 + oa + kAHalf, pa + 64 * kC);
            cp16(dW0 + ow, pw);
            cp16(dW0 + ow + kWHalf, pw + 64 * kC);
        }
        cp_commit();
    };

    issue(0, 0);
    issue(1, 1);

    float acc[2][8][4];
#pragma unroll
    for (int a = 0; a < 2; a++)
#pragma unroll
        for (int b = 0; b < 8; b++)
#pragma unroll
            for (int ci = 0; ci < 4; ci++) acc[a][b][ci] = 0.f;

    int buf = 0;
#pragma unroll 1
    for (int kc = 0; kc < 32; kc++) {
        if (kc < 30) cp_wait<1>(); else cp_wait<0>();
        __syncthreads();
        if (kc + 2 < 32) {
            int ns = buf + 2; if (ns >= 3) ns -= 3;
            issue(ns, kc + 2);
        }
#pragma unroll
        for (int sub = 0; sub < 2; sub++) {
            const uint32_t* aS = sm + buf * kAStageW + sub * kASubW;
            const uint32_t* wS = sm + kWBaseW + buf * kWStageW + sub * kWSubW;

            uint32_t a0[2][4], a1[2][4];
#pragma unroll
            for (int mt = 0; mt < 2; mt++) {
                const uint32_t* p = aS + (wm * 32 + mt * 16 + gid) * 20 + tig;
                a0[mt][0] = p[0];    a0[mt][1] = p[8 * 20];
                a0[mt][2] = p[4];    a0[mt][3] = p[8 * 20 + 4];
                a1[mt][0] = p[8];    a1[mt][1] = p[8 * 20 + 8];
                a1[mt][2] = p[12];   a1[mt][3] = p[8 * 20 + 12];
            }
#pragma unroll
            for (int grp = 0; grp < 2; grp++) {
                uint4 bf[4];
#pragma unroll
                for (int j = 0; j < 4; j++) {
                    int nt = grp * 4 + j;
                    bf[j] = *reinterpret_cast<const uint4*>(
                        wS + (wn * 64 + nt * 8 + gid) * 16 + tig * 4);
                }
#pragma unroll
                for (int j = 0; j < 4; j++) {
                    int nt = grp * 4 + j;
                    mma_tf32(acc[0][nt], a0[0][0], a0[0][1], a0[0][2], a0[0][3], bf[j].x, bf[j].y);
                    mma_tf32(acc[1][nt], a0[1][0], a0[1][1], a0[1][2], a0[1][3], bf[j].x, bf[j].y);
                    mma_tf32(acc[0][nt], a1[0][0], a1[0][1], a1[0][2], a1[0][3], bf[j].z, bf[j].w);
                    mma_tf32(acc[1][nt], a1[1][0], a1[1][1], a1[1][2], a1[1][3], bf[j].z, bf[j].w);
                }
            }
        }
        buf++; if (buf == 3) buf = 0;
    }

    const float* bias = (by == 0) ? g_b : (by == 1) ? th_b : ph_b;
    const float bscale = (by == 1) ? kLog2e : 1.0f;
    float* outp = (by == 0) ? g_glob : (by == 1) ? th_glob : ph_glob;
#pragma unroll
    for (int mt = 0; mt < 2; mt++)
#pragma unroll
        for (int nt = 0; nt < 8; nt++)
#pragma unroll
            for (int ci = 0; ci < 4; ci++) {
                int r = wm * 32 + mt * 16 + gid + ((ci >= 2) ? 8 : 0);
                int n = wn * 64 + nt * 8 + tig * 2 + (ci & 1);
                outp[(size_t)(row0 + r) * kD + n] =
                    acc[mt][nt][ci] + bias[n] * bscale;
            }
}

// ========================= K2: attention (MUFU-bound) =========================
__global__ void __launch_bounds__(256)
attn_kernel() {
    __shared__ float tgs[8][256];

    const int lane = threadIdx.x & 31;
    const int wid  = threadIdx.x >> 5;
    const int r    = blockIdx.x * 8 + wid;

    {
        float4 t4 = *reinterpret_cast<const float4*>(th_glob + (size_t)r * kD + lane * 4);
        float4 g4 = *reinterpret_cast<const float4*>(g_glob + (size_t)r * kD + lane * 4);
        float4* d = reinterpret_cast<float4*>(&tgs[wid][lane * 8]);
        d[0] = make_float4(t4.x, g4.x, t4.y, g4.y);
        d[1] = make_float4(t4.z, g4.z, t4.w, g4.w);
    }
    const float* pr = ph_glob + (size_t)r * kD;
    float p0 = pr[lane], p1 = pr[lane + 32], p2 = pr[lane + 64], p3 = pr[lane + 96];
    __syncwarp();

    const float2* tgr = reinterpret_cast<const float2*>(tgs[wid]);
    float n0 = 0.f, n1 = 0.f, n2 = 0.f, n3 = 0.f;
    float d0 = 0.f, d1 = 0.f, d2 = 0.f, d3 = 0.f;
#pragma unroll 8
    for (int j = 0; j < kD; j++) {
        float2 t = tgr[j];
        float e0 = fast_ex2(p0 * t.x);
        float e1 = fast_ex2(p1 * t.x);
        float e2 = fast_ex2(p2 * t.x);
        float e3 = fast_ex2(p3 * t.x);
        d0 += e0; d1 += e1; d2 += e2; d3 += e3;
        n0 = fmaf(e0, t.y, n0);
        n1 = fmaf(e1, t.y, n1);
        n2 = fmaf(e2, t.y, n2);
        n3 = fmaf(e3, t.y, n3);
    }
    float* yr = y_glob + (size_t)r * kD;
    yr[permc(lane)]      = __uint_as_float(f2tf(n0 * fast_rcp(d0)));
    yr[permc(lane + 32)] = __uint_as_float(f2tf(n1 * fast_rcp(d1)));
    yr[permc(lane + 64)] = __uint_as_float(f2tf(n2 * fast_rcp(d2)));
    yr[permc(lane + 96)] = __uint_as_float(f2tf(n3 * fast_rcp(d3)));
}

// ====== K3: out = y@W_w^T + W_b + x0 — W in smem, y via LDG.128 from L2 ======
// grid (128 row-tiles, 8 col-tiles), 256 thr, tile 128x128.
__global__ void __launch_bounds__(256, 2)
out_kernel(const float* __restrict__ x0, const float* __restrict__ Wb,
           float* __restrict__ out) {
    extern __shared__ uint32_t wbuf[];   // 8 sub-blocks of [128][16]

    const int tid  = threadIdx.x;
    const int lane = tid & 31;
    const int wid  = tid >> 5;
    const int gid  = lane >> 2;
    const int tig  = lane & 3;
    const int wm   = wid >> 1;           // 0..3 (32 rows)
    const int wn   = wid & 1;            // 0..1 (64 cols)
    const int row0 = blockIdx.x * 128;
    const int col0 = blockIdx.y * 128;

    // stage W tile [col0..col0+128) x 128 k-words: 4096 float4 / 256 thr
    {
        const uint32_t base = smem_u32(wbuf);
        const int r8 = tid >> 5;                 // 0..7
        const int cc = (tid & 31) * 4;           // word col 0..124
        const int sub = cc >> 4;                 // 0..7
        const int ccin = cc & 15;
#pragma unroll
        for (int i = 0; i < 16; i++) {
            int n = i * 8 + r8;                  // 0..127
            cp16(base + (sub * 2048 + n * 16 + ccin) * 4,
                 w3_glob + (size_t)(col0 + n) * kD + cc);
        }
        cp_commit();
    }
    cp_wait<0>();
    __syncthreads();

    float acc[2][8][4];
#pragma unroll
    for (int a = 0; a < 2; a++)
#pragma unroll
        for (int b = 0; b < 8; b++)
#pragma unroll
            for (int c = 0; c < 4; c++) acc[a][b][c] = 0.f;

    const int rbase = wm * 32;
    const uint32_t* y0 = reinterpret_cast<const uint32_t*>(y_glob) +
                         (size_t)(row0 + rbase + gid) * kD + tig * 4;
    // prefetch chunk 0 fragments (L2-resident y, contiguous via permuted layout)
    uint4 av[2][2];
#pragma unroll
    for (int mt = 0; mt < 2; mt++) {
        av[mt][0] = *reinterpret_cast<const uint4*>(y0 + (mt * 16) * kD);
        av[mt][1] = *reinterpret_cast<const uint4*>(y0 + (mt * 16 + 8) * kD);
    }

#pragma unroll 1
    for (int c = 0; c < 8; c++) {
        uint4 nx[2][2];
        if (c < 7) {
#pragma unroll
            for (int mt = 0; mt < 2; mt++) {
                nx[mt][0] = *reinterpret_cast<const uint4*>(y0 + (mt * 16) * kD + (c + 1) * 16);
                nx[mt][1] = *reinterpret_cast<const uint4*>(y0 + (mt * 16 + 8) * kD + (c + 1) * 16);
            }
        }
        const uint32_t* wS = wbuf + c * 2048;
#pragma unroll
        for (int grp = 0; grp < 2; grp++) {
            uint4 bv[4];
#pragma unroll
            for (int j = 0; j < 4; j++) {
                int nt = grp * 4 + j;
                bv[j] = *reinterpret_cast<const uint4*>(
                    wS + (wn * 64 + nt * 8 + gid) * 16 + tig * 4);
            }
#pragma unroll
            for (int j = 0; j < 4; j++) {
                int nt = grp * 4 + j;
#pragma unroll
                for (int mt = 0; mt < 2; mt++) {
                    mma_tf32(acc[mt][nt], av[mt][0].x, av[mt][1].x,
                             av[mt][0].y, av[mt][1].y, bv[j].x, bv[j].y);
                    mma_tf32(acc[mt][nt], av[mt][0].z, av[mt][1].z,
                             av[mt][0].w, av[mt][1].w, bv[j].z, bv[j].w);
                }
            }
        }
        if (c < 7) {
#pragma unroll
            for (int mt = 0; mt < 2; mt++) {
                av[mt][0] = nx[mt][0];
                av[mt][1] = nx[mt][1];
            }
        }
    }

#pragma unroll
    for (int mt = 0; mt < 2; mt++)
#pragma unroll
        for (int nt = 0; nt < 8; nt++)
#pragma unroll
            for (int pair = 0; pair < 2; pair++) {
                int r = rbase + mt * 16 + gid + pair * 8;
                int n = col0 + wn * 64 + nt * 8 + tig * 2;
                float2 xx = *reinterpret_cast<const float2*>(
                    x0 + (size_t)(row0 + r) * kC + n);
                float2 o;
                o.x = acc[mt][nt][pair * 2 + 0] + Wb[n] + xx.x;
                o.y = acc[mt][nt][pair * 2 + 1] + Wb[n + 1] + xx.y;
                *reinterpret_cast<float2*>(out + (size_t)(row0 + r) * kC + n) = o;
            }
}

extern "C" void kernel_launch(void* const* d_in, const int* in_sizes, int n_in,
                              void* d_out, int out_size) {
    (void)in_sizes; (void)n_in; (void)out_size;
    const float* x0   = (const float*)d_in[0];
    const float* x1   = (const float*)d_in[1];
    const float* g_w  = (const float*)d_in[2];
    const float* g_b  = (const float*)d_in[3];
    const float* th_w = (const float*)d_in[4];
    const float* th_b = (const float*)d_in[5];
    const float* ph_w = (const float*)d_in[6];
    const float* ph_b = (const float*)d_in[7];
    const float* Ww   = (const float*)d_in[8];
    const float* Wb   = (const float*)d_in[9];
    float* out = (float*)d_out;

    cudaFuncSetAttribute(proj_kernel,
                         cudaFuncAttributeMaxDynamicSharedMemorySize, kK1Smem);
    cudaFuncSetAttribute(out_kernel,
                         cudaFuncAttributeMaxDynamicSharedMemorySize, kK3Smem);

    conv_w_kernel<<<512, 256>>>(g_w, th_w, ph_w, Ww);
    proj_kernel<<<dim3(128, 3), 256, kK1Smem>>>(x0, x1, g_b, th_b, ph_b);
    attn_kernel<<<2048, 256>>>();
    out_kernel<<<dim3(128, 8), 256, kK3Smem>>>(x0, Wb, out);
}